// round 1
// baseline (speedup 1.0000x reference)
#include <cuda_runtime.h>

// Equivariant 'sum' variant:
//   out[b,m,o] = relu( sum_f x[b,m,f]*lam[f,o]  -  sum_f (sum_m x[b,m,f]) * gam[f,o] )
// B=8192, M=512, F=64, O=128, fp32.
//
// One CTA per b. x[b] tile (512x64 f32 = 128KB) + lam (64x128 = 32KB) staged in smem.
// Main GEMM uses packed fma.rn.f32x2 (FFMA2) with an 8m x 8o per-thread tile.

#define Bv 8192
#define Mv 512
#define Fv 64
#define Ov 128

typedef unsigned long long u64;

__device__ __forceinline__ u64 pack2(float x) {
    u64 r;
    asm("mov.b64 %0, {%1, %1};" : "=l"(r) : "f"(x));
    return r;
}

__device__ __forceinline__ void fma2(u64 &d, u64 a, u64 b) {
    asm("fma.rn.f32x2 %0, %1, %2, %0;" : "+l"(d) : "l"(a), "l"(b));
}

__device__ __forceinline__ void unpack2(u64 v, float &lo, float &hi) {
    asm("mov.b64 {%0, %1}, %2;" : "=f"(lo), "=f"(hi) : "l"(v));
}

extern __shared__ float smem[];

__global__ __launch_bounds__(256, 1)
void eq_kernel(const float* __restrict__ x,
               const float* __restrict__ lam,
               const float* __restrict__ gam,
               float* __restrict__ out)
{
    float* xs     = smem;              // 32768 floats: x[b] tile, [m][f], m-major
    float* lams   = smem + 32768;      //  8192 floats: lam [f][o]
    float* sred   = lams + 8192;       //   256 floats: partial sums over m
    float* pooled = sred + 256;        //   128 floats: pooled[o]

    const int b = blockIdx.x;
    const int t = threadIdx.x;

    // ---- Phase A: stage x[b] and lam in smem (vectorized, coalesced) ----
    {
        const float4* xg  = (const float4*)(x + (size_t)b * (Mv * Fv));
        float4*       xs4 = (float4*)xs;
        #pragma unroll
        for (int i = 0; i < 32; i++)
            xs4[t + 256 * i] = xg[t + 256 * i];

        const float4* lg  = (const float4*)lam;
        float4*       ls4 = (float4*)lams;
        #pragma unroll
        for (int i = 0; i < 8; i++)
            ls4[t + 256 * i] = lg[t + 256 * i];
    }
    __syncthreads();

    // ---- Phase B: s[f] = sum_m x[m,f]  (4 partial chunks of 128 rows) ----
    {
        const int f = t & 63;
        const int c = t >> 6;
        float acc = 0.f;
        const int mbeg = c * 128;
        #pragma unroll 8
        for (int m = mbeg; m < mbeg + 128; m++)
            acc += xs[m * Fv + f];
        sred[c * 64 + f] = acc;
    }
    __syncthreads();
    if (t < 64)
        sred[t] = sred[t] + sred[64 + t] + sred[128 + t] + sred[192 + t];
    __syncthreads();

    // ---- Phase C: pooled[o] = sum_f s[f] * gam[f,o] ----
    if (t < 128) {
        float p = 0.f;
        #pragma unroll
        for (int f = 0; f < 64; f++)
            p += sred[f] * gam[f * Ov + t];
        pooled[t] = p;
    }
    __syncthreads();

    // ---- Phase D: out[m,o] = relu( x@lam - pooled ) ----
    // Thread layout: to = t&15 (o dim), tm = t>>4 (m dim).
    // Per-thread tile: 8 m-rows x 8 o-cols (4 f32x2 pairs).
    // o pairs at 32*j + 2*to  -> warp's LDS.64 on lam covers all 32 banks once.
    const int to = t & 15;
    const int tm = t >> 4;

    float2 pl[4];
    #pragma unroll
    for (int j = 0; j < 4; j++)
        pl[j] = *(const float2*)&pooled[32 * j + 2 * to];

    float* outb = out + (size_t)b * (Mv * Ov);

    #pragma unroll 1
    for (int iter = 0; iter < 4; iter++) {
        const int m0 = iter * 128 + tm * 8;

        u64 acc[8][4];
        #pragma unroll
        for (int i = 0; i < 8; i++)
            #pragma unroll
            for (int j = 0; j < 4; j++)
                acc[i][j] = 0ull;  // (0.f, 0.f)

        #pragma unroll 4
        for (int f = 0; f < 64; f++) {
            u64 lv[4];
            #pragma unroll
            for (int j = 0; j < 4; j++)
                lv[j] = *(const u64*)&lams[f * Ov + 32 * j + 2 * to];

            #pragma unroll
            for (int i = 0; i < 8; i++) {
                u64 xp = pack2(xs[(m0 + i) * Fv + f]);
                #pragma unroll
                for (int j = 0; j < 4; j++)
                    fma2(acc[i][j], xp, lv[j]);
            }
        }

        // Epilogue: subtract pooled, relu, coalesced float2 stores.
        #pragma unroll
        for (int i = 0; i < 8; i++) {
            float* orow = outb + (size_t)(m0 + i) * Ov;
            #pragma unroll
            for (int j = 0; j < 4; j++) {
                float lo, hi;
                unpack2(acc[i][j], lo, hi);
                float2 r;
                r.x = fmaxf(lo - pl[j].x, 0.f);
                r.y = fmaxf(hi - pl[j].y, 0.f);
                *(float2*)&orow[32 * j + 2 * to] = r;
            }
        }
    }
}

extern "C" void kernel_launch(void* const* d_in, const int* in_sizes, int n_in,
                              void* d_out, int out_size)
{
    (void)in_sizes; (void)n_in; (void)out_size;
    const float* x   = (const float*)d_in[0];
    const float* lam = (const float*)d_in[1];
    const float* gam = (const float*)d_in[2];
    float* out = (float*)d_out;

    const size_t smem_bytes = (32768 + 8192 + 256 + 128) * sizeof(float); // 165376
    cudaFuncSetAttribute(eq_kernel, cudaFuncAttributeMaxDynamicSharedMemorySize,
                         (int)smem_bytes);

    eq_kernel<<<Bv, 256, smem_bytes>>>(x, lam, gam, out);
}

// round 3
// speedup vs baseline: 1.3481x; 1.3481x over previous
#include <cuda_runtime.h>
#include <cstdint>

#define Bv 8192
#define Mv 512
#define Fv 64
#define Ov 128

// ---- smem byte offsets ----
#define SM_XH   0         // x hi  bf16: 512 rows * 128B (chunk-XOR swizzled)
#define SM_XL   65536     // x lo  bf16
#define SM_LH   131072    // lam^T hi bf16: 128 rows(o) * 128B
#define SM_LL   147456    // lam^T lo
#define SM_SRED 163840    // 32 x 64 f32 partial column sums (8192B)
#define SM_POOL 172032    // pooled[128] f32 (512B)
#define SMEM_BYTES 172544

__device__ __forceinline__ uint32_t cvta_smem(const void* p) {
    uint32_t a;
    asm("{ .reg .u64 t; cvta.to.shared.u64 t, %1; cvt.u32.u64 %0, t; }" : "=r"(a) : "l"(p));
    return a;
}

// pack two f32 -> bf16x2 (first arg -> low half)
__device__ __forceinline__ uint32_t pack_bf16x2(float lo, float hi) {
    uint32_t r;
    asm("cvt.rn.bf16x2.f32 %0, %1, %2;" : "=r"(r) : "f"(hi), "f"(lo));
    return r;
}

__device__ __forceinline__ void ldsm4(uint32_t addr, uint32_t r[4]) {
    asm volatile("ldmatrix.sync.aligned.m8n8.x4.shared.b16 {%0,%1,%2,%3}, [%4];"
        : "=r"(r[0]), "=r"(r[1]), "=r"(r[2]), "=r"(r[3]) : "r"(addr));
}

__device__ __forceinline__ void hmma(float d[4], const uint32_t a[4], const uint32_t b[2]) {
    asm volatile("mma.sync.aligned.m16n8k16.row.col.f32.bf16.bf16.f32 "
        "{%0,%1,%2,%3}, {%4,%5,%6,%7}, {%8,%9}, {%0,%1,%2,%3};"
        : "+f"(d[0]), "+f"(d[1]), "+f"(d[2]), "+f"(d[3])
        : "r"(a[0]), "r"(a[1]), "r"(a[2]), "r"(a[3]), "r"(b[0]), "r"(b[1]));
}

// split float pair into bf16 hi part (h) and residual lo part (l)
__device__ __forceinline__ void split2(float v0, float v1, uint32_t &h, uint32_t &l) {
    h = pack_bf16x2(v0, v1);
    const float h0 = __uint_as_float(h << 16);
    const float h1 = __uint_as_float(h & 0xFFFF0000u);
    l = pack_bf16x2(v0 - h0, v1 - h1);
}

extern __shared__ char smem[];

__global__ __launch_bounds__(512, 1)
void eq_mma_kernel(const float* __restrict__ x,
                   const float* __restrict__ lam,
                   const float* __restrict__ gam,
                   float* __restrict__ out)
{
    const uint32_t sb = cvta_smem(smem);
    const int t = threadIdx.x;
    const int b = blockIdx.x;

    // ---- Phase A: x[b] fp32 -> bf16 hi/lo smem (swizzled) + partial column sums ----
    {
        const float4* xg = (const float4*)(x + (size_t)b * (Mv * Fv));
        const int f4 = t & 15;            // which float4 within a row
        const int tm = t >> 4;            // row phase (0..31)
        const int chunk = f4 >> 1;        // 16B chunk index (0..7)
        const int half = f4 & 1;          // which 8B half of the chunk
        float4 s4 = make_float4(0.f, 0.f, 0.f, 0.f);
        #pragma unroll 4
        for (int i = 0; i < 16; i++) {
            const int m = tm + 32 * i;
            const float4 v = xg[m * 16 + f4];
            s4.x += v.x; s4.y += v.y; s4.z += v.z; s4.w += v.w;
            uint32_t h01, l01, h23, l23;
            split2(v.x, v.y, h01, l01);
            split2(v.z, v.w, h23, l23);
            const uint32_t off = (uint32_t)(m * 128 + ((chunk ^ (m & 7)) << 4) + half * 8);
            *(uint2*)(smem + SM_XH + off) = make_uint2(h01, h23);
            *(uint2*)(smem + SM_XL + off) = make_uint2(l01, l23);
        }
        *(float4*)(smem + SM_SRED + (tm * 64 + f4 * 4) * 4) = s4;
    }

    // ---- Phase B: lam^T -> bf16 hi/lo smem (rows = o, 64 f per row, swizzled) ----
    {
        const int o = t & 127;
        const int q = t >> 7;             // 0..3, covers 8 f-pairs each
        #pragma unroll
        for (int j = 0; j < 8; j++) {
            const int fp = q * 8 + j;     // bf16 pair index (f = 2fp, 2fp+1)
            const float v0 = lam[(2 * fp) * Ov + o];
            const float v1 = lam[(2 * fp + 1) * Ov + o];
            uint32_t h, l;
            split2(v0, v1, h, l);
            const uint32_t off = (uint32_t)(o * 128 + (((fp >> 2) ^ (o & 7)) << 4) + (fp & 3) * 4);
            *(uint32_t*)(smem + SM_LH + off) = h;
            *(uint32_t*)(smem + SM_LL + off) = l;
        }
    }
    __syncthreads();

    // ---- finalize s[f] = sum_m x[m,f] ----
    if (t < 64) {
        float v = 0.f;
        #pragma unroll
        for (int r = 0; r < 32; r++)
            v += *(const float*)(smem + SM_SRED + (r * 64 + t) * 4);
        *(float*)(smem + SM_SRED + t * 4) = v;
    }
    __syncthreads();

    // ---- pooled[o] = sum_f s[f] * gam[f,o] (exact fp32) ----
    if (t < 128) {
        float p = 0.f;
        #pragma unroll
        for (int f = 0; f < 64; f++)
            p += *(const float*)(smem + SM_SRED + f * 4) * gam[f * Ov + t];
        *(float*)(smem + SM_POOL + t * 4) = p;
    }
    __syncthreads();

    // ---- Main: per-warp 32 rows x 128 cols via mma.sync bf16, 3 passes ----
    const int w = t >> 5;
    const int lane = t & 31;
    const int m0 = w * 32;

    // ldmatrix lane address components
    const int am  = lane & 15;                       // A row within 16-row tile
    const int acs = lane >> 4;                       // A chunk select (k lo/hi 8)
    const int bo  = (lane & 7) | ((lane & 16) >> 1); // B row within 16-row (o) group
    const int bcs = (lane >> 3) & 1;                 // B chunk select

    const uint32_t arow_off = (uint32_t)((m0 + am) * 128);
    const int asw = am & 7;
    const int bsw = bo & 7;

    const float* poolp = (const float*)(smem + SM_POOL);
    float* outb = out + (size_t)b * (Mv * Ov);

    const int g   = lane >> 2;
    const int tg2 = (lane & 3) * 2;

    #pragma unroll 1
    for (int nh = 0; nh < 2; nh++) {
        const int o0 = nh * 64;
        float acc[2][8][4];
        #pragma unroll
        for (int i = 0; i < 2; i++)
            #pragma unroll
            for (int j = 0; j < 8; j++)
                #pragma unroll
                for (int c = 0; c < 4; c++)
                    acc[i][j][c] = 0.f;

        #pragma unroll
        for (int pass = 0; pass < 3; pass++) {
            const uint32_t abase = sb + (pass == 2 ? SM_XL : SM_XH);
            const uint32_t bbase = sb + (pass == 1 ? SM_LL : SM_LH);
            #pragma unroll
            for (int k = 0; k < 4; k++) {
                uint32_t a0[4], a1[4];
                const uint32_t aadr = abase + arow_off
                                    + (uint32_t)((((k << 1) | acs) ^ asw) << 4);
                ldsm4(aadr, a0);
                ldsm4(aadr + 16 * 128, a1);    // mtile1: rows +16, same swizzle
                #pragma unroll
                for (int np = 0; np < 4; np++) {
                    const uint32_t badr = bbase
                        + (uint32_t)((o0 + np * 16 + bo) * 128)
                        + (uint32_t)((((k << 1) | bcs) ^ bsw) << 4);
                    uint32_t bf[4];
                    ldsm4(badr, bf);
                    hmma(acc[0][2 * np],     a0, bf);
                    hmma(acc[0][2 * np + 1], a0, bf + 2);
                    hmma(acc[1][2 * np],     a1, bf);
                    hmma(acc[1][2 * np + 1], a1, bf + 2);
                }
            }
        }

        // epilogue: subtract pooled, relu, store
        #pragma unroll
        for (int mt = 0; mt < 2; mt++) {
            #pragma unroll
            for (int nf = 0; nf < 8; nf++) {
                const int col = o0 + nf * 8 + tg2;
                const float2 pl = *(const float2*)&poolp[col];
                float* r0 = outb + (size_t)(m0 + mt * 16 + g) * Ov + col;
                float2 v0, v1;
                v0.x = fmaxf(acc[mt][nf][0] - pl.x, 0.f);
                v0.y = fmaxf(acc[mt][nf][1] - pl.y, 0.f);
                v1.x = fmaxf(acc[mt][nf][2] - pl.x, 0.f);
                v1.y = fmaxf(acc[mt][nf][3] - pl.y, 0.f);
                *(float2*)r0 = v0;
                *(float2*)(r0 + 8 * Ov) = v1;
            }
        }
    }
}

extern "C" void kernel_launch(void* const* d_in, const int* in_sizes, int n_in,
                              void* d_out, int out_size)
{
    (void)in_sizes; (void)n_in; (void)out_size;
    const float* x   = (const float*)d_in[0];
    const float* lam = (const float*)d_in[1];
    const float* gam = (const float*)d_in[2];
    float* out = (float*)d_out;

    cudaFuncSetAttribute(eq_mma_kernel, cudaFuncAttributeMaxDynamicSharedMemorySize,
                         SMEM_BYTES);
    eq_mma_kernel<<<Bv, 512, SMEM_BYTES>>>(x, lam, gam, out);
}

// round 4
// speedup vs baseline: 2.0720x; 1.5369x over previous
#include <cuda_runtime.h>
#include <cstdint>

#define Bv 8192
#define Mv 512
#define Fv 64
#define Ov 128

// ---- smem byte offsets ----
#define SM_XH   0         // x bf16: 512 rows * 128B (chunk-XOR swizzled) = 65536
#define SM_LH   65536     // lam^T bf16: 128 rows(o) * 128B              = 16384
#define SM_SRED 81920     // 32 x 64 f32 partial column sums             = 8192
#define SM_POOL 90112     // pooled[128] f32                             = 512
#define SMEM_BYTES 90624

__device__ __forceinline__ uint32_t cvta_smem(const void* p) {
    uint32_t a;
    asm("{ .reg .u64 t; cvta.to.shared.u64 t, %1; cvt.u32.u64 %0, t; }" : "=r"(a) : "l"(p));
    return a;
}

// pack two f32 -> bf16x2 (first arg -> low half)
__device__ __forceinline__ uint32_t pack_bf16x2(float lo, float hi) {
    uint32_t r;
    asm("cvt.rn.bf16x2.f32 %0, %1, %2;" : "=r"(r) : "f"(hi), "f"(lo));
    return r;
}

__device__ __forceinline__ void ldsm4(uint32_t addr, uint32_t r[4]) {
    asm volatile("ldmatrix.sync.aligned.m8n8.x4.shared.b16 {%0,%1,%2,%3}, [%4];"
        : "=r"(r[0]), "=r"(r[1]), "=r"(r[2]), "=r"(r[3]) : "r"(addr));
}

__device__ __forceinline__ void hmma(float d[4], const uint32_t a[4], const uint32_t b[2]) {
    asm volatile("mma.sync.aligned.m16n8k16.row.col.f32.bf16.bf16.f32 "
        "{%0,%1,%2,%3}, {%4,%5,%6,%7}, {%8,%9}, {%0,%1,%2,%3};"
        : "+f"(d[0]), "+f"(d[1]), "+f"(d[2]), "+f"(d[3])
        : "r"(a[0]), "r"(a[1]), "r"(a[2]), "r"(a[3]), "r"(b[0]), "r"(b[1]));
}

extern __shared__ char smem[];

__global__ __launch_bounds__(512, 1)
void eq_mma1_kernel(const float* __restrict__ x,
                    const float* __restrict__ lam,
                    const float* __restrict__ gam,
                    float* __restrict__ out)
{
    const uint32_t sb = cvta_smem(smem);
    const int t = threadIdx.x;
    const int b = blockIdx.x;

    // ---- Phase A: x[b] fp32 -> bf16 smem (swizzled) + partial column sums ----
    {
        const float4* xg = (const float4*)(x + (size_t)b * (Mv * Fv));
        const int f4 = t & 15;            // which float4 within a row
        const int tm = t >> 4;            // row phase (0..31)
        const int chunk = f4 >> 1;        // 16B chunk index (0..7)
        const int half = f4 & 1;          // which 8B half of the chunk
        float4 s4 = make_float4(0.f, 0.f, 0.f, 0.f);
        #pragma unroll 4
        for (int i = 0; i < 16; i++) {
            const int m = tm + 32 * i;
            const float4 v = xg[m * 16 + f4];
            s4.x += v.x; s4.y += v.y; s4.z += v.z; s4.w += v.w;
            const uint32_t h01 = pack_bf16x2(v.x, v.y);
            const uint32_t h23 = pack_bf16x2(v.z, v.w);
            const uint32_t off = (uint32_t)(m * 128 + ((chunk ^ (m & 7)) << 4) + half * 8);
            *(uint2*)(smem + SM_XH + off) = make_uint2(h01, h23);
        }
        *(float4*)(smem + SM_SRED + (tm * 64 + f4 * 4) * 4) = s4;
    }

    // ---- Phase B: lam^T -> bf16 smem (rows = o, 64 f per row, swizzled) ----
    {
        const int o = t & 127;
        const int q = t >> 7;             // 0..3, covers 8 f-pairs each
        #pragma unroll
        for (int j = 0; j < 8; j++) {
            const int fp = q * 8 + j;     // bf16 pair index (f = 2fp, 2fp+1)
            const float v0 = lam[(2 * fp) * Ov + o];
            const float v1 = lam[(2 * fp + 1) * Ov + o];
            const uint32_t h = pack_bf16x2(v0, v1);
            const uint32_t off = (uint32_t)(o * 128 + (((fp >> 2) ^ (o & 7)) << 4) + (fp & 3) * 4);
            *(uint32_t*)(smem + SM_LH + off) = h;
        }
    }
    __syncthreads();

    // ---- finalize s[f] = sum_m x[m,f] ----
    if (t < 64) {
        float v = 0.f;
        #pragma unroll
        for (int r = 0; r < 32; r++)
            v += *(const float*)(smem + SM_SRED + (r * 64 + t) * 4);
        *(float*)(smem + SM_SRED + t * 4) = v;
    }
    __syncthreads();

    // ---- pooled[o] = sum_f s[f] * gam[f,o] (exact fp32) ----
    if (t < 128) {
        float p = 0.f;
        #pragma unroll
        for (int f = 0; f < 64; f++)
            p += *(const float*)(smem + SM_SRED + f * 4) * gam[f * Ov + t];
        *(float*)(smem + SM_POOL + t * 4) = p;
    }
    __syncthreads();

    // ---- Main: per-warp 32 rows x 128 cols, single bf16 pass ----
    const int w = t >> 5;
    const int lane = t & 31;
    const int m0 = w * 32;

    const int am  = lane & 15;                       // A row within 16-row tile
    const int acs = lane >> 4;                       // A chunk select (k lo/hi 8)
    const int bo  = (lane & 7) | ((lane & 16) >> 1); // B row within 16-row (o) group
    const int bcs = (lane >> 3) & 1;                 // B chunk select

    const uint32_t arow_off = (uint32_t)((m0 + am) * 128);
    const int asw = am & 7;
    const int bsw = bo & 7;

    // Hoist ALL A-fragments (x) once: 4 k-slices x 2 m-tiles x 4 regs = 32 regs
    uint32_t afr[4][2][4];
    #pragma unroll
    for (int k = 0; k < 4; k++) {
        const uint32_t aadr = sb + SM_XH + arow_off
                            + (uint32_t)((((k << 1) | acs) ^ asw) << 4);
        ldsm4(aadr, afr[k][0]);
        ldsm4(aadr + 16 * 128, afr[k][1]);
    }

    const float* poolp = (const float*)(smem + SM_POOL);
    float* outb = out + (size_t)b * (Mv * Ov);

    const int g   = lane >> 2;
    const int tg2 = (lane & 3) * 2;

    #pragma unroll 1
    for (int nh = 0; nh < 2; nh++) {
        const int o0 = nh * 64;
        float acc[2][8][4];
        #pragma unroll
        for (int i = 0; i < 2; i++)
            #pragma unroll
            for (int j = 0; j < 8; j++)
                #pragma unroll
                for (int c = 0; c < 4; c++)
                    acc[i][j][c] = 0.f;

        #pragma unroll
        for (int k = 0; k < 4; k++) {
            #pragma unroll
            for (int np = 0; np < 4; np++) {
                const uint32_t badr = sb + SM_LH
                    + (uint32_t)((o0 + np * 16 + bo) * 128)
                    + (uint32_t)((((k << 1) | bcs) ^ bsw) << 4);
                uint32_t bf[4];
                ldsm4(badr, bf);
                hmma(acc[0][2 * np],     afr[k][0], bf);
                hmma(acc[0][2 * np + 1], afr[k][0], bf + 2);
                hmma(acc[1][2 * np],     afr[k][1], bf);
                hmma(acc[1][2 * np + 1], afr[k][1], bf + 2);
            }
        }

        // epilogue: subtract pooled, relu, store
        #pragma unroll
        for (int mt = 0; mt < 2; mt++) {
            #pragma unroll
            for (int nf = 0; nf < 8; nf++) {
                const int col = o0 + nf * 8 + tg2;
                const float2 pl = *(const float2*)&poolp[col];
                float* r0 = outb + (size_t)(m0 + mt * 16 + g) * Ov + col;
                float2 v0, v1;
                v0.x = fmaxf(acc[mt][nf][0] - pl.x, 0.f);
                v0.y = fmaxf(acc[mt][nf][1] - pl.y, 0.f);
                v1.x = fmaxf(acc[mt][nf][2] - pl.x, 0.f);
                v1.y = fmaxf(acc[mt][nf][3] - pl.y, 0.f);
                *(float2*)r0 = v0;
                *(float2*)(r0 + 8 * Ov) = v1;
            }
        }
    }
}

extern "C" void kernel_launch(void* const* d_in, const int* in_sizes, int n_in,
                              void* d_out, int out_size)
{
    (void)in_sizes; (void)n_in; (void)out_size;
    const float* x   = (const float*)d_in[0];
    const float* lam = (const float*)d_in[1];
    const float* gam = (const float*)d_in[2];
    float* out = (float*)d_out;

    cudaFuncSetAttribute(eq_mma1_kernel, cudaFuncAttributeMaxDynamicSharedMemorySize,
                         SMEM_BYTES);
    eq_mma1_kernel<<<Bv, 512, SMEM_BYTES>>>(x, lam, gam, out);
}

// round 5
// speedup vs baseline: 2.6725x; 1.2898x over previous
#include <cuda_runtime.h>
#include <cstdint>

#define Bv 8192
#define Mv 512
#define Fv 64
#define Ov 128

// ---- smem byte offsets ----
#define SM_XH   0         // x bf16: 512 rows * 128B (chunk-XOR swizzled) = 65536
#define SM_LH   65536     // lam^T bf16: 128 rows(o) * 128B              = 16384
#define SM_SRED 81920     // 16 x 64 f32 partial column sums             = 4096
#define SM_POOL 86016     // pooled[128] f32                             = 512
#define SMEM_BYTES 86528

__device__ __forceinline__ uint32_t cvta_smem(const void* p) {
    uint32_t a;
    asm("{ .reg .u64 t; cvta.to.shared.u64 t, %1; cvt.u32.u64 %0, t; }" : "=r"(a) : "l"(p));
    return a;
}

// pack two f32 -> bf16x2 (first arg -> low half)
__device__ __forceinline__ uint32_t pack_bf16x2(float lo, float hi) {
    uint32_t r;
    asm("cvt.rn.bf16x2.f32 %0, %1, %2;" : "=r"(r) : "f"(hi), "f"(lo));
    return r;
}

__device__ __forceinline__ void ldsm4(uint32_t addr, uint32_t r[4]) {
    asm volatile("ldmatrix.sync.aligned.m8n8.x4.shared.b16 {%0,%1,%2,%3}, [%4];"
        : "=r"(r[0]), "=r"(r[1]), "=r"(r[2]), "=r"(r[3]) : "r"(addr));
}

__device__ __forceinline__ void hmma(float d[4], const uint32_t a[4], const uint32_t b[2]) {
    asm volatile("mma.sync.aligned.m16n8k16.row.col.f32.bf16.bf16.f32 "
        "{%0,%1,%2,%3}, {%4,%5,%6,%7}, {%8,%9}, {%0,%1,%2,%3};"
        : "+f"(d[0]), "+f"(d[1]), "+f"(d[2]), "+f"(d[3])
        : "r"(a[0]), "r"(a[1]), "r"(a[2]), "r"(a[3]), "r"(b[0]), "r"(b[1]));
}

// streaming (evict-first) 128-bit global load / 64-bit store
__device__ __forceinline__ float4 ldg_cs4(const float4* p) {
    float4 v;
    asm volatile("ld.global.cs.v4.f32 {%0,%1,%2,%3}, [%4];"
        : "=f"(v.x), "=f"(v.y), "=f"(v.z), "=f"(v.w) : "l"(p));
    return v;
}
__device__ __forceinline__ void stg_cs2(float* p, float a, float b) {
    asm volatile("st.global.cs.v2.f32 [%0], {%1,%2};" :: "l"(p), "f"(a), "f"(b) : "memory");
}

extern __shared__ char smem[];

__global__ __launch_bounds__(256, 2)
void eq_mma2_kernel(const float* __restrict__ x,
                    const float* __restrict__ lam,
                    const float* __restrict__ gam,
                    float* __restrict__ out)
{
    const uint32_t sb = cvta_smem(smem);
    const int t = threadIdx.x;
    const int b = blockIdx.x;

    // ---- Phase A: x[b] fp32 -> bf16 smem (swizzled) + partial column sums ----
    {
        const float4* xg = (const float4*)(x + (size_t)b * (Mv * Fv));
        const int f4 = t & 15;            // which float4 within a row
        const int tm = t >> 4;            // row phase (0..15)
        const int chunk = f4 >> 1;        // 16B chunk index (0..7)
        const int half = f4 & 1;          // which 8B half of the chunk
        float4 s4 = make_float4(0.f, 0.f, 0.f, 0.f);
        #pragma unroll 8
        for (int i = 0; i < 32; i++) {
            const int m = tm + 16 * i;
            const float4 v = ldg_cs4(&xg[m * 16 + f4]);
            s4.x += v.x; s4.y += v.y; s4.z += v.z; s4.w += v.w;
            const uint32_t h01 = pack_bf16x2(v.x, v.y);
            const uint32_t h23 = pack_bf16x2(v.z, v.w);
            const uint32_t off = (uint32_t)(m * 128 + ((chunk ^ (m & 7)) << 4) + half * 8);
            *(uint2*)(smem + SM_XH + off) = make_uint2(h01, h23);
        }
        *(float4*)(smem + SM_SRED + (tm * 64 + f4 * 4) * 4) = s4;
    }

    // ---- Phase B: lam^T -> bf16 smem (rows = o, 64 f per row, swizzled) ----
    {
        const int o = t & 127;
        const int q = t >> 7;             // 0..1, covers 16 f-pairs each
        #pragma unroll 4
        for (int j = 0; j < 16; j++) {
            const int fp = q * 16 + j;    // bf16 pair index (f = 2fp, 2fp+1)
            const float v0 = lam[(2 * fp) * Ov + o];
            const float v1 = lam[(2 * fp + 1) * Ov + o];
            const uint32_t h = pack_bf16x2(v0, v1);
            const uint32_t off = (uint32_t)(o * 128 + (((fp >> 2) ^ (o & 7)) << 4) + (fp & 3) * 4);
            *(uint32_t*)(smem + SM_LH + off) = h;
        }
    }
    __syncthreads();

    // ---- finalize s[f] = sum_m x[m,f] ----
    if (t < 64) {
        float v = 0.f;
        #pragma unroll
        for (int r = 0; r < 16; r++)
            v += *(const float*)(smem + SM_SRED + (r * 64 + t) * 4);
        *(float*)(smem + SM_SRED + t * 4) = v;
    }
    __syncthreads();

    // ---- pooled[o] = sum_f s[f] * gam[f,o] (exact fp32) ----
    if (t < 128) {
        float p = 0.f;
        #pragma unroll
        for (int f = 0; f < 64; f++)
            p += *(const float*)(smem + SM_SRED + f * 4) * gam[f * Ov + t];
        *(float*)(smem + SM_POOL + t * 4) = p;
    }
    __syncthreads();

    // ---- Main: per-warp 64 rows x 128 cols, two 32-row sub-passes ----
    const int w = t >> 5;
    const int lane = t & 31;

    const int am  = lane & 15;                       // A row within 16-row tile
    const int acs = lane >> 4;                       // A chunk select (k lo/hi 8)
    const int bo  = (lane & 7) | ((lane & 16) >> 1); // B row within 16-row (o) group
    const int bcs = (lane >> 3) & 1;                 // B chunk select
    const int asw = am & 7;
    const int bsw = bo & 7;

    const float* poolp = (const float*)(smem + SM_POOL);
    float* outb = out + (size_t)b * (Mv * Ov);

    const int g   = lane >> 2;
    const int tg2 = (lane & 3) * 2;

    #pragma unroll 1
    for (int mp = 0; mp < 2; mp++) {
        const int m0 = w * 64 + mp * 32;
        const uint32_t arow_off = (uint32_t)((m0 + am) * 128);

        // Hoist A-fragments for these 32 rows: 4 k-slices x 2 m-tiles x 4 regs
        uint32_t afr[4][2][4];
        #pragma unroll
        for (int k = 0; k < 4; k++) {
            const uint32_t aadr = sb + SM_XH + arow_off
                                + (uint32_t)((((k << 1) | acs) ^ asw) << 4);
            ldsm4(aadr, afr[k][0]);
            ldsm4(aadr + 16 * 128, afr[k][1]);
        }

        #pragma unroll 1
        for (int nh = 0; nh < 2; nh++) {
            const int o0 = nh * 64;
            float acc[2][8][4];
            #pragma unroll
            for (int i = 0; i < 2; i++)
                #pragma unroll
                for (int j = 0; j < 8; j++)
                    #pragma unroll
                    for (int c = 0; c < 4; c++)
                        acc[i][j][c] = 0.f;

            #pragma unroll
            for (int k = 0; k < 4; k++) {
                #pragma unroll
                for (int np = 0; np < 4; np++) {
                    const uint32_t badr = sb + SM_LH
                        + (uint32_t)((o0 + np * 16 + bo) * 128)
                        + (uint32_t)((((k << 1) | bcs) ^ bsw) << 4);
                    uint32_t bf[4];
                    ldsm4(badr, bf);
                    hmma(acc[0][2 * np],     afr[k][0], bf);
                    hmma(acc[0][2 * np + 1], afr[k][0], bf + 2);
                    hmma(acc[1][2 * np],     afr[k][1], bf);
                    hmma(acc[1][2 * np + 1], afr[k][1], bf + 2);
                }
            }

            // epilogue: subtract pooled, relu, streaming stores
            #pragma unroll
            for (int mt = 0; mt < 2; mt++) {
                #pragma unroll
                for (int nf = 0; nf < 8; nf++) {
                    const int col = o0 + nf * 8 + tg2;
                    const float2 pl = *(const float2*)&poolp[col];
                    float* r0 = outb + (size_t)(m0 + mt * 16 + g) * Ov + col;
                    stg_cs2(r0,
                            fmaxf(acc[mt][nf][0] - pl.x, 0.f),
                            fmaxf(acc[mt][nf][1] - pl.y, 0.f));
                    stg_cs2(r0 + 8 * Ov,
                            fmaxf(acc[mt][nf][2] - pl.x, 0.f),
                            fmaxf(acc[mt][nf][3] - pl.y, 0.f));
                }
            }
        }
    }
}

extern "C" void kernel_launch(void* const* d_in, const int* in_sizes, int n_in,
                              void* d_out, int out_size)
{
    (void)in_sizes; (void)n_in; (void)out_size;
    const float* x   = (const float*)d_in[0];
    const float* lam = (const float*)d_in[1];
    const float* gam = (const float*)d_in[2];
    float* out = (float*)d_out;

    cudaFuncSetAttribute(eq_mma2_kernel, cudaFuncAttributeMaxDynamicSharedMemorySize,
                         SMEM_BYTES);
    eq_mma2_kernel<<<Bv, 256, SMEM_BYTES>>>(x, lam, gam, out);
}

// round 6
// speedup vs baseline: 2.8132x; 1.0527x over previous
#include <cuda_runtime.h>
#include <cstdint>

#define Bv 8192
#define Mv 512
#define Fv 64
#define Ov 128

// ---- smem byte offsets ----
#define SM_XH   0         // x bf16: 512 rows * 128B (chunk-XOR swizzled) = 65536
#define SM_LH   65536     // lam^T bf16 (row-permuted): 128 rows * 128B   = 16384
#define SM_SRED 81920     // 16 x 64 f32 partial column sums             = 4096
#define SM_POOL 86016     // pooled[128] f32 (real column order)         = 512
#define SMEM_BYTES 86528

__device__ __forceinline__ uint32_t cvta_smem(const void* p) {
    uint32_t a;
    asm("{ .reg .u64 t; cvta.to.shared.u64 t, %1; cvt.u32.u64 %0, t; }" : "=r"(a) : "l"(p));
    return a;
}

// pack two f32 -> bf16x2 (first arg -> low half)
__device__ __forceinline__ uint32_t pack_bf16x2(float lo, float hi) {
    uint32_t r;
    asm("cvt.rn.bf16x2.f32 %0, %1, %2;" : "=r"(r) : "f"(hi), "f"(lo));
    return r;
}

__device__ __forceinline__ void ldsm4(uint32_t addr, uint32_t r[4]) {
    asm volatile("ldmatrix.sync.aligned.m8n8.x4.shared.b16 {%0,%1,%2,%3}, [%4];"
        : "=r"(r[0]), "=r"(r[1]), "=r"(r[2]), "=r"(r[3]) : "r"(addr));
}

__device__ __forceinline__ void hmma(float d[4], const uint32_t a[4], const uint32_t b[2]) {
    asm volatile("mma.sync.aligned.m16n8k16.row.col.f32.bf16.bf16.f32 "
        "{%0,%1,%2,%3}, {%4,%5,%6,%7}, {%8,%9}, {%0,%1,%2,%3};"
        : "+f"(d[0]), "+f"(d[1]), "+f"(d[2]), "+f"(d[3])
        : "r"(a[0]), "r"(a[1]), "r"(a[2]), "r"(a[3]), "r"(b[0]), "r"(b[1]));
}

// streaming global accesses (touched once)
__device__ __forceinline__ float4 ldg_cs4(const float4* p) {
    float4 v;
    asm volatile("ld.global.cs.v4.f32 {%0,%1,%2,%3}, [%4];"
        : "=f"(v.x), "=f"(v.y), "=f"(v.z), "=f"(v.w) : "l"(p));
    return v;
}
__device__ __forceinline__ void stg_cs4(float* p, float a, float b, float c, float d) {
    asm volatile("st.global.cs.v4.f32 [%0], {%1,%2,%3,%4};"
        :: "l"(p), "f"(a), "f"(b), "f"(c), "f"(d) : "memory");
}

extern __shared__ char smem[];

__global__ __launch_bounds__(256, 2)
void eq_mma3_kernel(const float* __restrict__ x,
                    const float* __restrict__ lam,
                    const float* __restrict__ gam,
                    float* __restrict__ out)
{
    const uint32_t sb = cvta_smem(smem);
    const int t = threadIdx.x;
    const int b = blockIdx.x;

    // ---- Phase A: x[b] fp32 -> bf16 smem (swizzled) + partial column sums ----
    {
        const float4* xg = (const float4*)(x + (size_t)b * (Mv * Fv));
        const int f4 = t & 15;            // which float4 within a row
        const int tm = t >> 4;            // row phase (0..15)
        const int chunk = f4 >> 1;        // 16B chunk index (0..7)
        const int half = f4 & 1;          // which 8B half of the chunk
        float4 s4 = make_float4(0.f, 0.f, 0.f, 0.f);
        #pragma unroll 8
        for (int i = 0; i < 32; i++) {
            const int m = tm + 16 * i;
            const float4 v = ldg_cs4(&xg[m * 16 + f4]);
            s4.x += v.x; s4.y += v.y; s4.z += v.z; s4.w += v.w;
            const uint32_t h01 = pack_bf16x2(v.x, v.y);
            const uint32_t h23 = pack_bf16x2(v.z, v.w);
            const uint32_t off = (uint32_t)(m * 128 + ((chunk ^ (m & 7)) << 4) + half * 8);
            *(uint2*)(smem + SM_XH + off) = make_uint2(h01, h23);
        }
        *(float4*)(smem + SM_SRED + (tm * 64 + f4 * 4) * 4) = s4;
    }

    // ---- Phase B: lam^T -> bf16 smem, ROW-PERMUTED within each 16-row group ----
    // real col o maps to smem row: (o & ~15) | p(o&15),  p(r)=((r&2)<<2)|((r>>2)<<1)|(r&1)
    // so that thread tg=lane&3 of fragment pair (A,B) owns real cols 4*tg..4*tg+3.
    {
        const int o = t & 127;            // real output column
        const int r = o & 15;
        const int orow = (o & ~15) | (((r & 2) << 2) | ((r >> 2) << 1) | (r & 1));
        const int q = t >> 7;             // 0..1, covers 16 f-pairs each
        #pragma unroll 4
        for (int j = 0; j < 16; j++) {
            const int fp = q * 16 + j;    // bf16 pair index (f = 2fp, 2fp+1)
            const float v0 = lam[(2 * fp) * Ov + o];
            const float v1 = lam[(2 * fp + 1) * Ov + o];
            const uint32_t h = pack_bf16x2(v0, v1);
            const uint32_t off = (uint32_t)(orow * 128
                + (((fp >> 2) ^ (orow & 7)) << 4) + (fp & 3) * 4);
            *(uint32_t*)(smem + SM_LH + off) = h;
        }
    }
    __syncthreads();

    // ---- finalize s[f] = sum_m x[m,f] ----
    if (t < 64) {
        float v = 0.f;
        #pragma unroll
        for (int r = 0; r < 16; r++)
            v += *(const float*)(smem + SM_SRED + (r * 64 + t) * 4);
        *(float*)(smem + SM_SRED + t * 4) = v;
    }
    __syncthreads();

    // ---- pooled[o] = sum_f s[f] * gam[f,o] (exact fp32, real col order) ----
    if (t < 128) {
        float p = 0.f;
        #pragma unroll
        for (int f = 0; f < 64; f++)
            p += *(const float*)(smem + SM_SRED + f * 4) * gam[f * Ov + t];
        *(float*)(smem + SM_POOL + t * 4) = p;
    }
    __syncthreads();

    // ---- Main: per-warp 64 rows x 128 cols, two 32-row sub-passes ----
    const int w = t >> 5;
    const int lane = t & 31;

    const int am  = lane & 15;                       // A row within 16-row tile
    const int acs = lane >> 4;                       // A chunk select (k lo/hi 8)
    const int bo  = (lane & 7) | ((lane & 16) >> 1); // B physical row within 16-group
    const int bcs = (lane >> 3) & 1;                 // B chunk select
    const int asw = am & 7;
    const int bsw = bo & 7;

    const float* poolp = (const float*)(smem + SM_POOL);
    float* outb = out + (size_t)b * (Mv * Ov);

    const int g  = lane >> 2;
    const int tg = lane & 3;

    #pragma unroll 1
    for (int mp = 0; mp < 2; mp++) {
        const int m0 = w * 64 + mp * 32;
        const uint32_t arow_off = (uint32_t)((m0 + am) * 128);

        // Hoist A-fragments for these 32 rows: 4 k-slices x 2 m-tiles x 4 regs
        uint32_t afr[4][2][4];
        #pragma unroll
        for (int k = 0; k < 4; k++) {
            const uint32_t aadr = sb + SM_XH + arow_off
                                + (uint32_t)((((k << 1) | acs) ^ asw) << 4);
            ldsm4(aadr, afr[k][0]);
            ldsm4(aadr + 16 * 128, afr[k][1]);
        }

        #pragma unroll 1
        for (int nh = 0; nh < 2; nh++) {
            const int o0 = nh * 64;
            float acc[2][8][4];
            #pragma unroll
            for (int i = 0; i < 2; i++)
                #pragma unroll
                for (int j = 0; j < 8; j++)
                    #pragma unroll
                    for (int c = 0; c < 4; c++)
                        acc[i][j][c] = 0.f;

            #pragma unroll
            for (int k = 0; k < 4; k++) {
                #pragma unroll
                for (int np = 0; np < 4; np++) {
                    const uint32_t badr = sb + SM_LH
                        + (uint32_t)((o0 + np * 16 + bo) * 128)
                        + (uint32_t)((((k << 1) | bcs) ^ bsw) << 4);
                    uint32_t bf[4];
                    ldsm4(badr, bf);
                    hmma(acc[0][2 * np],     afr[k][0], bf);
                    hmma(acc[0][2 * np + 1], afr[k][0], bf + 2);
                    hmma(acc[1][2 * np],     afr[k][1], bf);
                    hmma(acc[1][2 * np + 1], afr[k][1], bf + 2);
                }
            }

            // epilogue: fragment pair (2np, 2np+1) = real cols np*16+4*tg .. +3
            #pragma unroll
            for (int np = 0; np < 4; np++) {
                const int col = o0 + np * 16 + 4 * tg;
                const float4 pl = *(const float4*)&poolp[col];
                #pragma unroll
                for (int mt = 0; mt < 2; mt++) {
                    const float* a0 = acc[mt][2 * np];
                    const float* a1 = acc[mt][2 * np + 1];
                    float* r0 = outb + (size_t)(m0 + mt * 16 + g) * Ov + col;
                    stg_cs4(r0,
                            fmaxf(a0[0] - pl.x, 0.f), fmaxf(a0[1] - pl.y, 0.f),
                            fmaxf(a1[0] - pl.z, 0.f), fmaxf(a1[1] - pl.w, 0.f));
                    stg_cs4(r0 + 8 * Ov,
                            fmaxf(a0[2] - pl.x, 0.f), fmaxf(a0[3] - pl.y, 0.f),
                            fmaxf(a1[2] - pl.z, 0.f), fmaxf(a1[3] - pl.w, 0.f));
                }
            }
        }
    }
}

extern "C" void kernel_launch(void* const* d_in, const int* in_sizes, int n_in,
                              void* d_out, int out_size)
{
    (void)in_sizes; (void)n_in; (void)out_size;
    const float* x   = (const float*)d_in[0];
    const float* lam = (const float*)d_in[1];
    const float* gam = (const float*)d_in[2];
    float* out = (float*)d_out;

    cudaFuncSetAttribute(eq_mma3_kernel, cudaFuncAttributeMaxDynamicSharedMemorySize,
                         SMEM_BYTES);
    eq_mma3_kernel<<<Bv, 256, SMEM_BYTES>>>(x, lam, gam, out);
}